// round 12
// baseline (speedup 1.0000x reference)
#include <cuda_runtime.h>
#include <cuda_bf16.h>
#include <math.h>
#include <stdint.h>

#define B_    8
#define CIN   256
#define COUT  256
#define HH    64
#define WW    64
#define HW    4096
#define K2    9
#define KTOT  (CIN * K2)   // 2304
#define NCH   72           // K chunks of 32; kt' = k*256 + c  (k fixed per chunk)

typedef unsigned long long ull;

// Scratch: per (b, k, pixel): 4 corner indices + 4 corner weights (mask-premultiplied)
__device__ int   g_cidx[B_ * K2 * HW * 4];
__device__ float g_cwgt[B_ * K2 * HW * 4];
// Pre-converted tf32 weights, chunked: [chunk][oc][32 kt'-cols], 128B rows
__device__ uint32_t g_wB[NCH * 8192];

// ---------------- helpers ----------------
__device__ __forceinline__ ull fma2(ull a, ull b, ull c) {
    ull d;
    asm("fma.rn.f32x2 %0, %1, %2, %3;" : "=l"(d) : "l"(a), "l"(b), "l"(c));
    return d;
}
__device__ __forceinline__ ull pack2(float lo, float hi) {
    ull r;
    asm("mov.b64 %0, {%1, %2};" : "=l"(r) : "f"(lo), "f"(hi));
    return r;
}
__device__ __forceinline__ void unpack2(ull v, float& lo, float& hi) {
    asm("mov.b64 {%0, %1}, %2;" : "=f"(lo), "=f"(hi) : "l"(v));
}
__device__ __forceinline__ uint32_t smem_u32(const void* p) {
    return (uint32_t)__cvta_generic_to_shared(p);
}
__device__ __forceinline__ void cpa16(uint32_t dst, const void* src) {
    asm volatile("cp.async.ca.shared.global [%0], [%1], 16;" :: "r"(dst), "l"(src));
}
__device__ __forceinline__ void ldm_x4(uint32_t addr, uint32_t* r) {
    asm volatile("ldmatrix.sync.aligned.m8n8.x4.shared.b16 {%0,%1,%2,%3}, [%4];"
                 : "=r"(r[0]), "=r"(r[1]), "=r"(r[2]), "=r"(r[3]) : "r"(addr));
}
__device__ __forceinline__ uint32_t f2tf32(float f) {
    uint32_t r;
    asm("cvt.rna.tf32.f32 %0, %1;" : "=r"(r) : "f"(f));
    return r;
}
__device__ __forceinline__ void mma_tf32(float* d, const uint32_t* a,
                                         uint32_t b0, uint32_t b1) {
    asm volatile("mma.sync.aligned.m16n8k8.row.col.f32.tf32.tf32.f32 "
                 "{%0,%1,%2,%3}, {%4,%5,%6,%7}, {%8,%9}, {%0,%1,%2,%3};"
                 : "+f"(d[0]), "+f"(d[1]), "+f"(d[2]), "+f"(d[3])
                 : "r"(a[0]), "r"(a[1]), "r"(a[2]), "r"(a[3]), "r"(b0), "r"(b1));
}

// =====================================================================
// Kernel 0: convert main weight to tf32, kt' = k*256 + c ordering,
// chunked [cc][oc][32] for cp.async
// =====================================================================
__global__ void __launch_bounds__(256) prep_wB(const float* __restrict__ wgt)
{
    int i = blockIdx.x * 256 + threadIdx.x;    // 72*256*32 = 589824
    int ktl = i & 31;
    int oc  = (i >> 5) & 255;
    int cc  = i >> 13;
    int ktp = cc * 32 + ktl;                   // kt' = k*256 + c
    int k   = ktp >> 8;
    int c   = ktp & 255;
    float v = wgt[((size_t)oc * CIN + c) * 9 + k];
    g_wB[cc * 8192 + oc * 32 + ktl] = f2tf32(v);
}

// =====================================================================
// Stage 1: offset(18ch) + mask(9ch) 3x3 conv, 4 channels per barrier
// pair; fused epilogue emits bilinear corner indices/weights
// (mask-premultiplied).
// =====================================================================
__global__ void __launch_bounds__(128) prep_kernel(
    const float* __restrict__ x,
    const float* __restrict__ offw, const float* __restrict__ offb,
    const float* __restrict__ modw, const float* __restrict__ modb)
{
    __shared__ float xs[4][180];     // 4 ch x (10 x 18) halo
    __shared__ float ws2[4][252];    // 4 ch x [k][oc pad 28]

    const int b  = blockIdx.z;
    const int h0 = blockIdx.y * 8;
    const int w0 = blockIdx.x * 16;
    const int tid = threadIdx.x;
    const int th = tid >> 4, tw = tid & 15;
    const int h = h0 + th, w = w0 + tw;
    const float* xb = x + (size_t)b * CIN * HW;

    ull acc2[14];
#pragma unroll
    for (int i = 0; i < 14; i++) acc2[i] = 0ull;

    for (int c0 = 0; c0 < CIN; c0 += 4) {
        for (int i = tid; i < 720; i += 128) {
            int ch = i / 180, ii = i - ch * 180;
            int r = ii / 18, cc = ii - r * 18;
            int gh = h0 - 1 + r, gw = w0 - 1 + cc;
            float v = 0.f;
            if (gh >= 0 && gh < HH && gw >= 0 && gw < WW)
                v = xb[(c0 + ch) * HW + gh * WW + gw];
            xs[ch][ii] = v;
        }
        for (int i = tid; i < 1008; i += 128) {
            int ch = i / 252, jj = i - ch * 252;
            int k = jj / 28, oc = jj - k * 28;
            float v;
            if (oc < 18)      v = offw[(oc * CIN + c0 + ch) * 9 + k];
            else if (oc < 27) v = modw[((oc - 18) * CIN + c0 + ch) * 9 + k];
            else              v = 0.f;
            ws2[ch][jj] = v;
        }
        __syncthreads();

#pragma unroll
        for (int ch = 0; ch < 4; ch++) {
            ull wd[9];
#pragma unroll
            for (int k = 0; k < 9; k++) {
                float v = xs[ch][(th + k / 3) * 18 + tw + k % 3];
                wd[k] = pack2(v, v);
            }
#pragma unroll
            for (int k = 0; k < 9; k++) {
                const float* row = &ws2[ch][k * 28];
#pragma unroll
                for (int u = 0; u < 7; u++) {
                    ulonglong2 tt = *(const ulonglong2*)(row + u * 4);
                    acc2[2 * u]     = fma2(wd[k], tt.x, acc2[2 * u]);
                    acc2[2 * u + 1] = fma2(wd[k], tt.y, acc2[2 * u + 1]);
                }
            }
        }
        __syncthreads();
    }

    float acc[28];
#pragma unroll
    for (int u = 0; u < 14; u++) unpack2(acc2[u], acc[2 * u], acc[2 * u + 1]);

    const int pix = h * WW + w;
#pragma unroll
    for (int k = 0; k < 9; k++) {
        float dy = acc[2 * k]     + offb[2 * k];
        float dx = acc[2 * k + 1] + offb[2 * k + 1];
        float mz = acc[18 + k]    + modb[k];
        float m  = 2.f / (1.f + expf(-mz));

        float py = dy + (float)(h - 1 + k / 3);
        float px = dx + (float)(w - 1 + (k % 3));
        float y0f = floorf(py), x0f = floorf(px);
        float ly = py - y0f, lx = px - x0f;
        int y0 = (int)y0f, x0 = (int)x0f;

        int4 id; float4 wt;
        {
            int yy = y0, xx = x0; float wv = (1.f - ly) * (1.f - lx);
            bool v = (yy >= 0) && (yy < HH) && (xx >= 0) && (xx < WW);
            id.x = min(max(yy, 0), HH - 1) * WW + min(max(xx, 0), WW - 1);
            wt.x = v ? wv * m : 0.f;
        }
        {
            int yy = y0, xx = x0 + 1; float wv = (1.f - ly) * lx;
            bool v = (yy >= 0) && (yy < HH) && (xx >= 0) && (xx < WW);
            id.y = min(max(yy, 0), HH - 1) * WW + min(max(xx, 0), WW - 1);
            wt.y = v ? wv * m : 0.f;
        }
        {
            int yy = y0 + 1, xx = x0; float wv = ly * (1.f - lx);
            bool v = (yy >= 0) && (yy < HH) && (xx >= 0) && (xx < WW);
            id.z = min(max(yy, 0), HH - 1) * WW + min(max(xx, 0), WW - 1);
            wt.z = v ? wv * m : 0.f;
        }
        {
            int yy = y0 + 1, xx = x0 + 1; float wv = ly * lx;
            bool v = (yy >= 0) && (yy < HH) && (xx >= 0) && (xx < WW);
            id.w = min(max(yy, 0), HH - 1) * WW + min(max(xx, 0), WW - 1);
            wt.w = v ? wv * m : 0.f;
        }
        int slot = (b * K2 + k) * HW + pix;
        ((int4*)g_cidx)[slot]   = id;
        ((float4*)g_cwgt)[slot] = wt;
    }
}

// =====================================================================
// Stage 2: fused im2col + SINGLE-PASS TF32 warp-MMA GEMM, pipelined.
// (byte-identical to the R9 kernel that passed at 696 us)
// =====================================================================
#define NTH 512
#define APAD 144             // 32 tf32 = 128B + 16B pad (conflict-free)
#define BPAD 144
#define ABUF 18432           // 128 * 144
#define BBUF 36864           // 256 * 144
// smem byte offsets
#define SM_SAMPW 0           // 18432
#define SM_SAMPI 18432       // 9216
#define SM_A     27648       // 2 x 18432
#define SM_B     64512       // 2 x 36864
#define SMEM_BYTES 138240

__global__ void __launch_bounds__(NTH)
dconv_kernel(const float* __restrict__ x,
             const float* __restrict__ bias, float* __restrict__ out)
{
    extern __shared__ unsigned char sm[];
    const uint32_t smb = smem_u32(sm);
    float*  sampW = (float*)(sm + SM_SAMPW);
    short4* sampI = (short4*)(sm + SM_SAMPI);

    const int b = blockIdx.z;
    const int pixbase = blockIdx.x * 128;
    const int tid = threadIdx.x;
    const int lane = tid & 31;
    const int wid = tid >> 5;
    const int warp_m = (wid & 3) * 32;
    const int warp_n = (wid >> 2) * 64;
    const float* xb = x + (size_t)b * CIN * HW;

    // sampling tables for this block's 128 pixels
    for (int i = tid; i < 1152; i += NTH) {
        int k = i >> 7, p = i & 127;
        int slot = (b * K2 + k) * HW + pixbase + p;
        ((float4*)sampW)[i] = ((const float4*)g_cwgt)[slot];
        int4 id = ((const int4*)g_cidx)[slot];
        short4 s;
        s.x = (short)id.x; s.y = (short)id.y; s.z = (short)id.z; s.w = (short)id.w;
        sampI[i] = s;
    }
    __syncthreads();

    float acc[2][8][4];
#pragma unroll
    for (int mt = 0; mt < 2; mt++)
#pragma unroll
        for (int nb = 0; nb < 8; nb++)
#pragma unroll
            for (int r = 0; r < 4; r++) acc[mt][nb][r] = 0.f;

    const int pp = tid & 127;         // this thread's production pixel
    const int cq = tid >> 7;          // channel group: channels cq*8..cq*8+7

// issue cp.async of B chunk cc into buffer bb (32KB, 128B rows -> 144B rows)
#define B_ISSUE(cc, bb) do {                                                     \
    const unsigned char* _src = (const unsigned char*)(g_wB + (cc) * 8192);      \
    uint32_t _Bu = smb + SM_B + (bb) * BBUF;                                     \
    _Pragma("unroll")                                                            \
    for (int _t = 0; _t < 4; _t++) {                                             \
        int _j = _t * NTH + tid;                                                 \
        int _oc = _j >> 3, _seg = _j & 7;                                        \
        cpa16(_Bu + _oc * BPAD + _seg * 16, _src + _oc * 128 + _seg * 16);       \
    }                                                                            \
    asm volatile("cp.async.commit_group;" ::: "memory");                         \
} while (0)

// one K8 step of the tf32 GEMM on buffer bb; ks in 0..3
#define GEMM_KS(ks, bb) do {                                                     \
    uint32_t _Au = smb + SM_A + (bb) * ABUF;                                     \
    uint32_t _Bu = smb + SM_B + (bb) * BBUF;                                     \
    uint32_t _ah[2][4];                                                          \
    const int _arow = lane & 15;                                                 \
    const int _aoff = ((lane >> 4) << 4) + (ks) * 32;                            \
    _Pragma("unroll")                                                            \
    for (int _mt = 0; _mt < 2; _mt++) {                                          \
        ldm_x4(_Au + (uint32_t)((warp_m + _mt * 16 + _arow) * APAD + _aoff),     \
               _ah[_mt]);                                                        \
    }                                                                            \
    const int _brow = (lane & 7) + ((lane >> 4) << 3);                           \
    const int _boff = ((lane >> 3) & 1) * 16 + (ks) * 32;                        \
    _Pragma("unroll")                                                            \
    for (int _nt = 0; _nt < 4; _nt++) {                                          \
        uint32_t _bf[4];                                                         \
        ldm_x4(_Bu + (uint32_t)((warp_n + _nt * 16 + _brow) * BPAD + _boff),     \
               _bf);                                                             \
        _Pragma("unroll")                                                        \
        for (int _mt = 0; _mt < 2; _mt++) {                                      \
            mma_tf32(acc[_mt][_nt * 2],     _ah[_mt], _bf[0], _bf[1]);           \
            mma_tf32(acc[_mt][_nt * 2 + 1], _ah[_mt], _bf[2], _bf[3]);           \
        }                                                                        \
    }                                                                            \
} while (0)

    // ---- prologue: stage chunk 0 (k=0, channels 0..31) ----
    {
        B_ISSUE(0, 0);
        int si = pp;                   // (k=0) << 7 | pp
        short4 i4 = sampI[si];
        float4 w4 = ((const float4*)sampW)[si];
        const float* base = xb + (size_t)(cq * 8) * HW;
        const float* pa = base + i4.x;
        const float* pb = base + i4.y;
        const float* pc = base + i4.z;
        const float* pd = base + i4.w;
        uint32_t* Arow = (uint32_t*)(sm + SM_A + pp * APAD + cq * 32);
#pragma unroll
        for (int j = 0; j < 8; j++) {
            float v = w4.x * pa[j * HW] + w4.y * pb[j * HW]
                    + w4.z * pc[j * HW] + w4.w * pd[j * HW];
            Arow[j] = f2tf32(v);
        }
        asm volatile("cp.async.wait_group 0;" ::: "memory");
    }
    __syncthreads();

    // ---- main pipelined loop ----
    for (int c = 0; c < NCH; c++) {
        const int cur = c & 1;
        const int nxt = cur ^ 1;
        const bool more = (c < NCH - 1);

        float4 w4 = make_float4(0.f, 0.f, 0.f, 0.f);
        const float *pa = xb, *pb = xb, *pc = xb, *pd = xb;
        if (more) {
            B_ISSUE(c + 1, nxt);
            const int kn  = (c + 1) >> 3;
            const int c0n = ((c + 1) & 7) * 32;
            int si = (kn << 7) + pp;
            short4 i4 = sampI[si];
            w4 = ((const float4*)sampW)[si];
            const float* base = xb + (size_t)(c0n + cq * 8) * HW;
            pa = base + i4.x; pb = base + i4.y; pc = base + i4.z; pd = base + i4.w;
        }

        float pre[16];
#pragma unroll
        for (int j = 0; j < 16; j++) pre[j] = 0.f;
        if (more) {
#pragma unroll
            for (int j = 0; j < 4; j++) {
                pre[j * 4 + 0] = pa[j * HW];
                pre[j * 4 + 1] = pb[j * HW];
                pre[j * 4 + 2] = pc[j * HW];
                pre[j * 4 + 3] = pd[j * HW];
            }
        }

        GEMM_KS(0, cur);
        GEMM_KS(1, cur);

        if (more) {
            uint32_t av[4];
#pragma unroll
            for (int j = 0; j < 4; j++)
                av[j] = f2tf32(w4.x * pre[j * 4 + 0] + w4.y * pre[j * 4 + 1]
                             + w4.z * pre[j * 4 + 2] + w4.w * pre[j * 4 + 3]);
            *(uint4*)(sm + SM_A + nxt * ABUF + pp * APAD + cq * 32) =
                make_uint4(av[0], av[1], av[2], av[3]);
            // prefetch second half (channels +4..+7)
#pragma unroll
            for (int j = 0; j < 4; j++) {
                pre[j * 4 + 0] = pa[(j + 4) * HW];
                pre[j * 4 + 1] = pb[(j + 4) * HW];
                pre[j * 4 + 2] = pc[(j + 4) * HW];
                pre[j * 4 + 3] = pd[(j + 4) * HW];
            }
        }

        GEMM_KS(2, cur);
        GEMM_KS(3, cur);

        if (more) {
            uint32_t av[4];
#pragma unroll
            for (int j = 0; j < 4; j++)
                av[j] = f2tf32(w4.x * pre[j * 4 + 0] + w4.y * pre[j * 4 + 1]
                             + w4.z * pre[j * 4 + 2] + w4.w * pre[j * 4 + 3]);
            *(uint4*)(sm + SM_A + nxt * ABUF + pp * APAD + cq * 32 + 16) =
                make_uint4(av[0], av[1], av[2], av[3]);
        }

        asm volatile("cp.async.wait_group 0;" ::: "memory");
        __syncthreads();
    }

    // ---- epilogue ----
    float* ob = out + (size_t)b * COUT * HW + pixbase;
#pragma unroll
    for (int mt = 0; mt < 2; mt++)
#pragma unroll
        for (int nb = 0; nb < 8; nb++) {
            int col0 = warp_n + nb * 8 + (lane & 3) * 2;
            float b0 = __ldg(bias + col0);
            float b1 = __ldg(bias + col0 + 1);
            int row0 = warp_m + mt * 16 + (lane >> 2);
#pragma unroll
            for (int r = 0; r < 4; r++) {
                int row = row0 + ((r >> 1) & 1) * 8;
                int col = col0 + (r & 1);
                ob[(size_t)col * HW + row] = acc[mt][nb][r] + ((r & 1) ? b1 : b0);
            }
        }
}

extern "C" void kernel_launch(void* const* d_in, const int* in_sizes, int n_in,
                              void* d_out, int out_size)
{
    const float* x    = (const float*)d_in[0];
    const float* offw = (const float*)d_in[1];
    const float* offb = (const float*)d_in[2];
    const float* modw = (const float*)d_in[3];
    const float* modb = (const float*)d_in[4];
    const float* wgt  = (const float*)d_in[5];
    const float* bias = (const float*)d_in[6];
    float* out = (float*)d_out;

    static bool attr_done = false;
    if (!attr_done) {
        cudaFuncSetAttribute(dconv_kernel, cudaFuncAttributeMaxDynamicSharedMemorySize,
                             SMEM_BYTES);
        attr_done = true;
    }

    prep_wB<<<2304, 256>>>(wgt);                // 72*256*32 threads

    dim3 g1(4, 8, 8);
    prep_kernel<<<g1, 128>>>(x, offw, offb, modw, modb);

    dim3 g2(HW / 128, 1, 8);                    // 32 x 8 = 256 blocks
    dconv_kernel<<<g2, NTH, SMEM_BYTES>>>(x, bias, out);
}

// round 13
// speedup vs baseline: 1.1301x; 1.1301x over previous
#include <cuda_runtime.h>
#include <cuda_fp16.h>
#include <math.h>
#include <stdint.h>

#define B_    8
#define CIN   256
#define COUT  256
#define HH    64
#define WW    64
#define HW    4096
#define K2    9
#define KTOT  (CIN * K2)   // 2304
#define NCH   72           // K chunks of 32; kt' = k*256 + c  (k fixed per chunk)

typedef unsigned long long ull;

// Scratch: per (b, k, pixel): 4 corner indices + 4 corner weights (mask-premultiplied)
__device__ int   g_cidx[B_ * K2 * HW * 4];
__device__ float g_cwgt[B_ * K2 * HW * 4];
// Pre-converted fp16 weights, chunked: [chunk][oc][32 kt'-cols], 64B rows
__device__ __half g_wH[NCH * 8192];

// ---------------- helpers ----------------
__device__ __forceinline__ ull fma2(ull a, ull b, ull c) {
    ull d;
    asm("fma.rn.f32x2 %0, %1, %2, %3;" : "=l"(d) : "l"(a), "l"(b), "l"(c));
    return d;
}
__device__ __forceinline__ ull pack2(float lo, float hi) {
    ull r;
    asm("mov.b64 %0, {%1, %2};" : "=l"(r) : "f"(lo), "f"(hi));
    return r;
}
__device__ __forceinline__ void unpack2(ull v, float& lo, float& hi) {
    asm("mov.b64 {%0, %1}, %2;" : "=f"(lo), "=f"(hi) : "l"(v));
}
__device__ __forceinline__ uint32_t smem_u32(const void* p) {
    return (uint32_t)__cvta_generic_to_shared(p);
}
__device__ __forceinline__ void cpa16(uint32_t dst, const void* src) {
    asm volatile("cp.async.ca.shared.global [%0], [%1], 16;" :: "r"(dst), "l"(src));
}
__device__ __forceinline__ void ldm_x4(uint32_t addr, uint32_t* r) {
    asm volatile("ldmatrix.sync.aligned.m8n8.x4.shared.b16 {%0,%1,%2,%3}, [%4];"
                 : "=r"(r[0]), "=r"(r[1]), "=r"(r[2]), "=r"(r[3]) : "r"(addr));
}
__device__ __forceinline__ void mma_f16(float* d, const uint32_t* a,
                                        uint32_t b0, uint32_t b1) {
    asm volatile("mma.sync.aligned.m16n8k16.row.col.f32.f16.f16.f32 "
                 "{%0,%1,%2,%3}, {%4,%5,%6,%7}, {%8,%9}, {%0,%1,%2,%3};"
                 : "+f"(d[0]), "+f"(d[1]), "+f"(d[2]), "+f"(d[3])
                 : "r"(a[0]), "r"(a[1]), "r"(a[2]), "r"(a[3]), "r"(b0), "r"(b1));
}
__device__ __forceinline__ uint32_t h2pack(float a, float b) {
    __half2 h = __floats2half2_rn(a, b);
    return *(uint32_t*)&h;
}

// =====================================================================
// Kernel 0: convert main weight to fp16, kt' = k*256 + c ordering,
// chunked [cc][oc][32] for cp.async
// =====================================================================
__global__ void __launch_bounds__(256) prep_wB(const float* __restrict__ wgt)
{
    int i = blockIdx.x * 256 + threadIdx.x;    // 72*256*32 = 589824
    int ktl = i & 31;
    int oc  = (i >> 5) & 255;
    int cc  = i >> 13;
    int ktp = cc * 32 + ktl;                   // kt' = k*256 + c
    int k   = ktp >> 8;
    int c   = ktp & 255;
    float v = wgt[((size_t)oc * CIN + c) * 9 + k];
    g_wH[cc * 8192 + oc * 32 + ktl] = __float2half_rn(v);
}

// =====================================================================
// Stage 1: offset(18ch) + mask(9ch) 3x3 conv (R9 version — best known),
// fused epilogue emits bilinear corner indices/weights (mask-premult).
// =====================================================================
__global__ void __launch_bounds__(128) prep_kernel(
    const float* __restrict__ x,
    const float* __restrict__ offw, const float* __restrict__ offb,
    const float* __restrict__ modw, const float* __restrict__ modb)
{
    __shared__ float xs[10][18];
    __shared__ float ws2[9 * 28];

    const int b  = blockIdx.z;
    const int h0 = blockIdx.y * 8;
    const int w0 = blockIdx.x * 16;
    const int tid = threadIdx.x;
    const int th = tid >> 4, tw = tid & 15;
    const int h = h0 + th, w = w0 + tw;
    const float* xb = x + (size_t)b * CIN * HW;

    ull acc2[14];
#pragma unroll
    for (int i = 0; i < 14; i++) acc2[i] = 0ull;

    for (int c = 0; c < CIN; c++) {
        for (int i = tid; i < 180; i += 128) {
            int r = i / 18, cc = i - r * 18;
            int gh = h0 - 1 + r, gw = w0 - 1 + cc;
            float v = 0.f;
            if (gh >= 0 && gh < HH && gw >= 0 && gw < WW) v = xb[c * HW + gh * WW + gw];
            (&xs[0][0])[i] = v;
        }
        for (int i = tid; i < 252; i += 128) {
            int k = i / 28, oc = i - k * 28;
            float v;
            if (oc < 18)      v = offw[(oc * CIN + c) * 9 + k];
            else if (oc < 27) v = modw[((oc - 18) * CIN + c) * 9 + k];
            else              v = 0.f;
            ws2[i] = v;
        }
        __syncthreads();

        ull wd[9];
#pragma unroll
        for (int k = 0; k < 9; k++) {
            float v = xs[th + k / 3][tw + k % 3];
            wd[k] = pack2(v, v);
        }
#pragma unroll
        for (int k = 0; k < 9; k++) {
            const float* row = ws2 + k * 28;
#pragma unroll
            for (int u = 0; u < 7; u++) {
                ulonglong2 tt = *(const ulonglong2*)(row + u * 4);
                acc2[2 * u]     = fma2(wd[k], tt.x, acc2[2 * u]);
                acc2[2 * u + 1] = fma2(wd[k], tt.y, acc2[2 * u + 1]);
            }
        }
        __syncthreads();
    }

    float acc[28];
#pragma unroll
    for (int u = 0; u < 14; u++) unpack2(acc2[u], acc[2 * u], acc[2 * u + 1]);

    const int pix = h * WW + w;
#pragma unroll
    for (int k = 0; k < 9; k++) {
        float dy = acc[2 * k]     + offb[2 * k];
        float dx = acc[2 * k + 1] + offb[2 * k + 1];
        float mz = acc[18 + k]    + modb[k];
        float m  = 2.f / (1.f + expf(-mz));

        float py = dy + (float)(h - 1 + k / 3);
        float px = dx + (float)(w - 1 + (k % 3));
        float y0f = floorf(py), x0f = floorf(px);
        float ly = py - y0f, lx = px - x0f;
        int y0 = (int)y0f, x0 = (int)x0f;

        int4 id; float4 wt;
        {
            int yy = y0, xx = x0; float wv = (1.f - ly) * (1.f - lx);
            bool v = (yy >= 0) && (yy < HH) && (xx >= 0) && (xx < WW);
            id.x = min(max(yy, 0), HH - 1) * WW + min(max(xx, 0), WW - 1);
            wt.x = v ? wv * m : 0.f;
        }
        {
            int yy = y0, xx = x0 + 1; float wv = (1.f - ly) * lx;
            bool v = (yy >= 0) && (yy < HH) && (xx >= 0) && (xx < WW);
            id.y = min(max(yy, 0), HH - 1) * WW + min(max(xx, 0), WW - 1);
            wt.y = v ? wv * m : 0.f;
        }
        {
            int yy = y0 + 1, xx = x0; float wv = ly * (1.f - lx);
            bool v = (yy >= 0) && (yy < HH) && (xx >= 0) && (xx < WW);
            id.z = min(max(yy, 0), HH - 1) * WW + min(max(xx, 0), WW - 1);
            wt.z = v ? wv * m : 0.f;
        }
        {
            int yy = y0 + 1, xx = x0 + 1; float wv = ly * lx;
            bool v = (yy >= 0) && (yy < HH) && (xx >= 0) && (xx < WW);
            id.w = min(max(yy, 0), HH - 1) * WW + min(max(xx, 0), WW - 1);
            wt.w = v ? wv * m : 0.f;
        }
        int slot = (b * K2 + k) * HW + pix;
        ((int4*)g_cidx)[slot]   = id;
        ((float4*)g_cwgt)[slot] = wt;
    }
}

// =====================================================================
// Stage 2: fused im2col + SINGLE-PASS FP16 warp-MMA GEMM (m16n8k16),
// pipelined; kt' = k*256 + c ordering (one k per 32-chunk).
// Block: 128 pixels x 256 ocs, 512 thr / 16 warps (warp tile 32x64).
// =====================================================================
#define NTH 512
#define APAD 80              // 32 fp16 = 64B + 16B pad (conflict-free)
#define BPAD 80
#define ABUF 10240           // 128 * 80
#define BBUF 20480           // 256 * 80
// smem byte offsets
#define SM_SAMPW 0           // 18432
#define SM_SAMPI 18432       // 9216
#define SM_A     27648       // 2 x 10240
#define SM_B     48128       // 2 x 20480
#define SMEM_BYTES 89088

__global__ void __launch_bounds__(NTH)
dconv_kernel(const float* __restrict__ x,
             const float* __restrict__ bias, float* __restrict__ out)
{
    extern __shared__ unsigned char sm[];
    const uint32_t smb = smem_u32(sm);
    float*  sampW = (float*)(sm + SM_SAMPW);
    short4* sampI = (short4*)(sm + SM_SAMPI);

    const int b = blockIdx.z;
    const int pixbase = blockIdx.x * 128;
    const int tid = threadIdx.x;
    const int lane = tid & 31;
    const int wid = tid >> 5;
    const int warp_m = (wid & 3) * 32;
    const int warp_n = (wid >> 2) * 64;
    const float* xb = x + (size_t)b * CIN * HW;

    // sampling tables for this block's 128 pixels
    for (int i = tid; i < 1152; i += NTH) {
        int k = i >> 7, p = i & 127;
        int slot = (b * K2 + k) * HW + pixbase + p;
        ((float4*)sampW)[i] = ((const float4*)g_cwgt)[slot];
        int4 id = ((const int4*)g_cidx)[slot];
        short4 s;
        s.x = (short)id.x; s.y = (short)id.y; s.z = (short)id.z; s.w = (short)id.w;
        sampI[i] = s;
    }
    __syncthreads();

    float acc[2][8][4];
#pragma unroll
    for (int mt = 0; mt < 2; mt++)
#pragma unroll
        for (int nb = 0; nb < 8; nb++)
#pragma unroll
            for (int r = 0; r < 4; r++) acc[mt][nb][r] = 0.f;

    const int pp = tid & 127;         // this thread's production pixel
    const int cq = tid >> 7;          // channel group: channels cq*8..cq*8+7

// issue cp.async of B chunk cc into buffer bb (16KB, 64B rows -> 80B rows)
#define B_ISSUE(cc, bb) do {                                                     \
    const unsigned char* _src = (const unsigned char*)(g_wH + (cc) * 8192);      \
    uint32_t _Bu = smb + SM_B + (bb) * BBUF;                                     \
    _Pragma("unroll")                                                            \
    for (int _t = 0; _t < 2; _t++) {                                             \
        int _j = _t * NTH + tid;                                                 \
        int _oc = _j >> 2, _seg = _j & 3;                                        \
        cpa16(_Bu + _oc * BPAD + _seg * 16, _src + _oc * 64 + _seg * 16);        \
    }                                                                            \
    asm volatile("cp.async.commit_group;" ::: "memory");                         \
} while (0)

// one K16 step of the fp16 GEMM on buffer bb; ks in 0..1
#define GEMM_KS(ks, bb) do {                                                     \
    uint32_t _Au = smb + SM_A + (bb) * ABUF;                                     \
    uint32_t _Bu = smb + SM_B + (bb) * BBUF;                                     \
    uint32_t _ah[2][4];                                                          \
    const int _arow = lane & 15;                                                 \
    const int _aoff = ((lane >> 4) << 4) + (ks) * 32;                            \
    _Pragma("unroll")                                                            \
    for (int _mt = 0; _mt < 2; _mt++) {                                          \
        ldm_x4(_Au + (uint32_t)((warp_m + _mt * 16 + _arow) * APAD + _aoff),     \
               _ah[_mt]);                                                        \
    }                                                                            \
    _Pragma("unroll")                                                            \
    for (int _nt = 0; _nt < 4; _nt++) {                                          \
        uint32_t _bf[4];                                                         \
        ldm_x4(_Bu + (uint32_t)((warp_n + _nt * 16 + (lane & 15)) * BPAD         \
                                + ((lane >> 4) << 4) + (ks) * 32),               \
               _bf);                                                             \
        _Pragma("unroll")                                                        \
        for (int _mt = 0; _mt < 2; _mt++) {                                      \
            mma_f16(acc[_mt][_nt * 2],     _ah[_mt], _bf[0], _bf[2]);            \
            mma_f16(acc[_mt][_nt * 2 + 1], _ah[_mt], _bf[1], _bf[3]);            \
        }                                                                        \
    }                                                                            \
} while (0)

    // ---- prologue: stage chunk 0 (k=0, channels 0..31) ----
    {
        B_ISSUE(0, 0);
        short4 i4 = sampI[pp];
        float4 w4 = ((const float4*)sampW)[pp];
        const float* base = xb + (size_t)(cq * 8) * HW;
        const float* pa = base + i4.x;
        const float* pb = base + i4.y;
        const float* pc = base + i4.z;
        const float* pd = base + i4.w;
        uint32_t av[4];
#pragma unroll
        for (int j2 = 0; j2 < 4; j2++) {
            float v0 = w4.x * pa[(2 * j2) * HW] + w4.y * pb[(2 * j2) * HW]
                     + w4.z * pc[(2 * j2) * HW] + w4.w * pd[(2 * j2) * HW];
            float v1 = w4.x * pa[(2 * j2 + 1) * HW] + w4.y * pb[(2 * j2 + 1) * HW]
                     + w4.z * pc[(2 * j2 + 1) * HW] + w4.w * pd[(2 * j2 + 1) * HW];
            av[j2] = h2pack(v0, v1);
        }
        *(uint4*)(sm + SM_A + pp * APAD + cq * 16) = make_uint4(av[0], av[1], av[2], av[3]);
        asm volatile("cp.async.wait_group 0;" ::: "memory");
    }
    __syncthreads();

    // ---- main pipelined loop ----
    for (int c = 0; c < NCH; c++) {
        const int cur = c & 1;
        const int nxt = cur ^ 1;
        const bool more = (c < NCH - 1);

        float4 w4 = make_float4(0.f, 0.f, 0.f, 0.f);
        const float *pa = xb, *pb = xb, *pc = xb, *pd = xb;
        if (more) {
            B_ISSUE(c + 1, nxt);
            const int kn  = (c + 1) >> 3;
            const int c0n = ((c + 1) & 7) * 32;
            int si = (kn << 7) + pp;
            short4 i4 = sampI[si];
            w4 = ((const float4*)sampW)[si];
            const float* base = xb + (size_t)(c0n + cq * 8) * HW;
            pa = base + i4.x; pb = base + i4.y; pc = base + i4.z; pd = base + i4.w;
        }

        float pre[16];
#pragma unroll
        for (int j = 0; j < 16; j++) pre[j] = 0.f;
        if (more) {
#pragma unroll
            for (int j = 0; j < 4; j++) {
                pre[j * 4 + 0] = pa[j * HW];
                pre[j * 4 + 1] = pb[j * HW];
                pre[j * 4 + 2] = pc[j * HW];
                pre[j * 4 + 3] = pd[j * HW];
            }
        }

        GEMM_KS(0, cur);

        uint32_t av[4] = {0u, 0u, 0u, 0u};
        if (more) {
#pragma unroll
            for (int j2 = 0; j2 < 2; j2++) {
                float v0 = w4.x * pre[(2 * j2) * 4 + 0] + w4.y * pre[(2 * j2) * 4 + 1]
                         + w4.z * pre[(2 * j2) * 4 + 2] + w4.w * pre[(2 * j2) * 4 + 3];
                float v1 = w4.x * pre[(2 * j2 + 1) * 4 + 0] + w4.y * pre[(2 * j2 + 1) * 4 + 1]
                         + w4.z * pre[(2 * j2 + 1) * 4 + 2] + w4.w * pre[(2 * j2 + 1) * 4 + 3];
                av[j2] = h2pack(v0, v1);
            }
            // prefetch second half (channels +4..+7)
#pragma unroll
            for (int j = 0; j < 4; j++) {
                pre[j * 4 + 0] = pa[(j + 4) * HW];
                pre[j * 4 + 1] = pb[(j + 4) * HW];
                pre[j * 4 + 2] = pc[(j + 4) * HW];
                pre[j * 4 + 3] = pd[(j + 4) * HW];
            }
        }

        GEMM_KS(1, cur);

        if (more) {
#pragma unroll
            for (int j2 = 0; j2 < 2; j2++) {
                float v0 = w4.x * pre[(2 * j2) * 4 + 0] + w4.y * pre[(2 * j2) * 4 + 1]
                         + w4.z * pre[(2 * j2) * 4 + 2] + w4.w * pre[(2 * j2) * 4 + 3];
                float v1 = w4.x * pre[(2 * j2 + 1) * 4 + 0] + w4.y * pre[(2 * j2 + 1) * 4 + 1]
                         + w4.z * pre[(2 * j2 + 1) * 4 + 2] + w4.w * pre[(2 * j2 + 1) * 4 + 3];
                av[2 + j2] = h2pack(v0, v1);
            }
            *(uint4*)(sm + SM_A + nxt * ABUF + pp * APAD + cq * 16) =
                make_uint4(av[0], av[1], av[2], av[3]);
        }

        asm volatile("cp.async.wait_group 0;" ::: "memory");
        __syncthreads();
    }

    // ---- epilogue ----
    float* ob = out + (size_t)b * COUT * HW + pixbase;
#pragma unroll
    for (int mt = 0; mt < 2; mt++)
#pragma unroll
        for (int nb = 0; nb < 8; nb++) {
            int col0 = warp_n + nb * 8 + (lane & 3) * 2;
            float b0 = __ldg(bias + col0);
            float b1 = __ldg(bias + col0 + 1);
            int row0 = warp_m + mt * 16 + (lane >> 2);
#pragma unroll
            for (int r = 0; r < 4; r++) {
                int row = row0 + ((r >> 1) & 1) * 8;
                int col = col0 + (r & 1);
                ob[(size_t)col * HW + row] = acc[mt][nb][r] + ((r & 1) ? b1 : b0);
            }
        }
}

extern "C" void kernel_launch(void* const* d_in, const int* in_sizes, int n_in,
                              void* d_out, int out_size)
{
    const float* x    = (const float*)d_in[0];
    const float* offw = (const float*)d_in[1];
    const float* offb = (const float*)d_in[2];
    const float* modw = (const float*)d_in[3];
    const float* modb = (const float*)d_in[4];
    const float* wgt  = (const float*)d_in[5];
    const float* bias = (const float*)d_in[6];
    float* out = (float*)d_out;

    static bool attr_done = false;
    if (!attr_done) {
        cudaFuncSetAttribute(dconv_kernel, cudaFuncAttributeMaxDynamicSharedMemorySize,
                             SMEM_BYTES);
        attr_done = true;
    }

    prep_wB<<<2304, 256>>>(wgt);                // 72*256*32 threads

    dim3 g1(4, 8, 8);
    prep_kernel<<<g1, 128>>>(x, offw, offb, modw, modb);

    dim3 g2(HW / 128, 1, 8);                    // 32 x 8 = 256 blocks
    dconv_kernel<<<g2, NTH, SMEM_BYTES>>>(x, bias, out);
}